// round 8
// baseline (speedup 1.0000x reference)
#include <cuda_runtime.h>

// AssociatorLoss: B=32, N=32
//   one[b,i,j,k,l] = sum_m a[b,i,m,l] * a[b,j,k,m]
//   two[b,i,j,k,l] = sum_m a[b,m,k,l] * a[b,i,j,m]
//   KL = sum two * log(two/one) / B
//
// R7 (resubmitted after broker failure): lane = (k,l) layout. R6 was
// L1TEX-bound (72%) at 2.67 FMA per LDS instruction. Now lanes span
// 4k x 8(l/4) so contiguous reads are LDS.128 (512B/instr) and per-thread
// tile is 4j x 1k x 4l float4: 512 LDS per 4096 FFMA per warp (8 FMA/LDS,
// 3x fewer LSU instructions). Plain SMEM layout, all hot-loop addresses
// [base+imm], live regs ~100.

__device__ float g_partial[1024];
__device__ int   g_count = 0;

// Accurate natural log: reduce to z in [sqrt(2)/2, sqrt(2)), atanh series.
// |abs err| ~1e-7; keeps the 33M-term KL sum far inside the 1e-3 tolerance.
__device__ __forceinline__ float acc_logf(float x) {
    int ix = __float_as_int(x);
    int t  = ix - 0x3f3504f3;
    int e  = t >> 23;
    float z = __int_as_float(ix - (t & 0xff800000));
    float f = z - 1.0f;
    float s = __fdividef(f, 2.0f + f);
    float s2 = s * s;
    float p = fmaf(s2, fmaf(s2, fmaf(s2, 0.28571429f, 0.4f), 0.66666667f), 2.0f);
    return fmaf((float)e, 0.69314718f, s * p);
}

__global__ __launch_bounds__(512, 1)
void assoc_kernel(const float* __restrict__ A, float* __restrict__ out) {
    extern __shared__ float4 sc4[];             // 8192 float4, PLAIN layout
    // float4 index of a[x,y,l4] = x*256 + y*8 + l4

    const int i = blockIdx.x;                   // 0..31
    const int b = blockIdx.y;                   // 0..31
    const int tid = threadIdx.x;
    const float4* ab4 = reinterpret_cast<const float4*>(A + b * 32768);

    // ---- stage a[b] (128 KB) into SMEM, plain copy, coalesced ----
    #pragma unroll
    for (int it = 0; it < 16; ++it)
        sc4[it * 512 + tid] = ab4[it * 512 + tid];
    __syncthreads();

    const int lane = tid & 31;
    const int w    = tid >> 5;       // warp 0..15
    const int kq   = lane >> 3;      // 0..3 : k within warp's k-group
    const int lq   = lane & 7;       // 0..7 : l-chunk (4 l's each)
    const int jb   = (w & 7) * 4;    // 8 j-groups of 4
    const int khi  = w >> 3;         // k-half (0/1)

    const int sibase = i * 256 + lq;        // + m*8 : a[i,m,l-chunk]
    const int ajbase = i * 256 + jb * 8;    // + jt*8 + mc : a[i,j,m-chunk]

    float kl = 0.0f;

    #pragma unroll 1
    for (int p = 0; p < 4; ++p) {               // 4 phases, 4 k (via lanes) each
        const int kk    = khi * 16 + p * 4 + kq;  // this thread's k
        const int vbase = kk * 8 + lq;            // + m*256 : a[m,k,l-chunk]
        const int rbase = jb * 256 + kk * 8;      // + jt*256 + mc : a[j,k,m-chunk]

        float4 acc1[4], acc2[4];
        #pragma unroll
        for (int jt = 0; jt < 4; ++jt) {
            acc1[jt] = make_float4(0.f, 0.f, 0.f, 0.f);
            acc2[jt] = make_float4(0.f, 0.f, 0.f, 0.f);
        }

        #pragma unroll
        for (int mc = 0; mc < 8; ++mc) {        // m = mc*4 + mm
            float4 aj4[4], rj4[4];
            #pragma unroll
            for (int jt = 0; jt < 4; ++jt) {
                aj4[jt] = sc4[ajbase + jt * 8 + mc];    // a[i,jb+jt,m..] bcast
                rj4[jt] = sc4[rbase + jt * 256 + mc];   // a[jb+jt,k,m..] 4-addr
            }

            #pragma unroll
            for (int mm = 0; mm < 4; ++mm) {
                const int m = mc * 4 + mm;
                float4 sm = sc4[sibase + m * 8];        // a[i,m,l..]  8-addr
                float4 v  = sc4[vbase + m * 256];       // a[m,k,l..]  32-addr

                #pragma unroll
                for (int jt = 0; jt < 4; ++jt) {
                    float av = ((const float*)&aj4[jt])[mm];
                    float rv = ((const float*)&rj4[jt])[mm];
                    acc2[jt].x = fmaf(av, v.x,  acc2[jt].x);
                    acc2[jt].y = fmaf(av, v.y,  acc2[jt].y);
                    acc2[jt].z = fmaf(av, v.z,  acc2[jt].z);
                    acc2[jt].w = fmaf(av, v.w,  acc2[jt].w);
                    acc1[jt].x = fmaf(rv, sm.x, acc1[jt].x);
                    acc1[jt].y = fmaf(rv, sm.y, acc1[jt].y);
                    acc1[jt].z = fmaf(rv, sm.z, acc1[jt].z);
                    acc1[jt].w = fmaf(rv, sm.w, acc1[jt].w);
                }
            }
        }

        // ---- KL for this 4j x 4l tile: two * log(two/one) ----
        #pragma unroll
        for (int jt = 0; jt < 4; ++jt) {
            const float* t2 = (const float*)&acc2[jt];
            const float* t1 = (const float*)&acc1[jt];
            #pragma unroll
            for (int e = 0; e < 4; ++e) {
                float two = t2[e], one = t1[e];
                kl = fmaf(two, acc_logf(__fdividef(two, one)), kl);
            }
        }
    }

    // ---- deterministic block reduction ----
    #pragma unroll
    for (int o = 16; o > 0; o >>= 1)
        kl += __shfl_xor_sync(0xffffffffu, kl, o);

    __shared__ float sred[16];
    __shared__ bool  s_last;
    if ((tid & 31) == 0) sred[w] = kl;
    __syncthreads();

    if (tid == 0) {
        float s = 0.0f;
        #pragma unroll
        for (int x = 0; x < 16; ++x) s += sred[x];
        g_partial[b * 32 + i] = s;
        __threadfence();
        s_last = (atomicAdd(&g_count, 1) == 1023);
    }
    __syncthreads();

    // ---- last CTA: deterministic double-precision final reduce ----
    if (s_last && tid < 32) {
        __threadfence();
        double s = 0.0;
        #pragma unroll
        for (int it = 0; it < 32; ++it)
            s += (double)g_partial[it * 32 + tid];
        #pragma unroll
        for (int o = 16; o > 0; o >>= 1)
            s += __shfl_xor_sync(0xffffffffu, s, o);
        if (tid == 0) {
            out[0] = (float)(s * (1.0 / 32.0));   // / B
            g_count = 0;                          // reset for next graph replay
        }
    }
}

extern "C" void kernel_launch(void* const* d_in, const int* in_sizes, int n_in,
                              void* d_out, int out_size) {
    const float* A = (const float*)d_in[0];
    float* out = (float*)d_out;

    cudaFuncSetAttribute(assoc_kernel,
                         cudaFuncAttributeMaxDynamicSharedMemorySize, 131072);

    dim3 grid(32, 32);   // (i, b)
    assoc_kernel<<<grid, 512, 131072>>>(A, out);
}

// round 9
// speedup vs baseline: 1.4371x; 1.4371x over previous
#include <cuda_runtime.h>

// AssociatorLoss: B=32, N=32
//   one[b,i,j,k,l] = sum_m a[b,i,m,l] * a[b,j,k,m]
//   two[b,i,j,k,l] = sum_m a[b,m,k,l] * a[b,i,j,m]
//   KL = sum two * log(two/one) / B
//
// R9: packed fp32 via PTX fma.rn.f32x2 (Blackwell FFMA2; ptxas never emits
// it from C++). Halves the FFMA issue count -> SMSP floor 32.8K -> 16.4K
// cyc/wave. Lane=(kq,lq) layout from R7 (LDS.128 everywhere, 8 FMA/LDS);
// accumulators are b64 l-pairs taken directly from the vector loads; only
// the broadcast scalars need a mov.b64 {r,r} dup (ALU pipe, fits FFMA2
// rt=2 gaps). Live regs ~90 (acc 32 + prefetch 32 + operands) to stay off
// the 128-reg spill cliff that burned R0/R4/R5/R7.

__device__ float g_partial[1024];
__device__ int   g_count = 0;

typedef unsigned long long u64;

// d = a *2 b +2 d   (packed fp32 pairs)
#define FMA2(acc, a, b) \
    asm("fma.rn.f32x2 %0, %1, %2, %0;" : "+l"(acc) : "l"(a), "l"(b))

__device__ __forceinline__ u64 dup2(float x) {
    u64 r; unsigned u = __float_as_uint(x);
    asm("mov.b64 %0, {%1, %1};" : "=l"(r) : "r"(u));
    return r;
}
__device__ __forceinline__ void unpack2(u64 v, float& lo, float& hi) {
    unsigned a, b;
    asm("mov.b64 {%0, %1}, %2;" : "=r"(a), "=r"(b) : "l"(v));
    lo = __uint_as_float(a); hi = __uint_as_float(b);
}

// Accurate natural log: reduce to z in [sqrt(2)/2, sqrt(2)), atanh series.
// |abs err| ~1e-7; keeps the 33M-term KL sum far inside the 1e-3 tolerance.
__device__ __forceinline__ float acc_logf(float x) {
    int ix = __float_as_int(x);
    int t  = ix - 0x3f3504f3;
    int e  = t >> 23;
    float z = __int_as_float(ix - (t & 0xff800000));
    float f = z - 1.0f;
    float s = __fdividef(f, 2.0f + f);
    float s2 = s * s;
    float p = fmaf(s2, fmaf(s2, fmaf(s2, 0.28571429f, 0.4f), 0.66666667f), 2.0f);
    return fmaf((float)e, 0.69314718f, s * p);
}

__global__ __launch_bounds__(512, 1)
void assoc_kernel(const float* __restrict__ A, float* __restrict__ out) {
    extern __shared__ float4 sc4[];             // 8192 float4, PLAIN layout
    // float4 index of a[x,y,l4] = x*256 + y*8 + l4

    const int i = blockIdx.x;                   // 0..31
    const int b = blockIdx.y;                   // 0..31
    const int tid = threadIdx.x;
    const float4* ab4 = reinterpret_cast<const float4*>(A + b * 32768);

    // ---- stage a[b] (128 KB) into SMEM, plain copy, coalesced ----
    #pragma unroll
    for (int it = 0; it < 16; ++it)
        sc4[it * 512 + tid] = ab4[it * 512 + tid];
    __syncthreads();

    const int lane = tid & 31;
    const int w    = tid >> 5;       // warp 0..15
    const int kq   = lane >> 3;      // 0..3 : k within warp's k-group
    const int lq   = lane & 7;       // 0..7 : l-chunk (4 l's -> 2 pairs)
    const int jb   = (w & 7) * 4;    // 8 j-groups of 4
    const int khi  = w >> 3;         // k-half (0/1)

    const int sibase = i * 256 + lq;        // + m*8 : a[i,m,l-chunk]
    const int ajbase = i * 256 + jb * 8;    // + jt*8 + mc : a[i,j,m-chunk]

    float kl = 0.0f;

    #pragma unroll 1
    for (int p = 0; p < 4; ++p) {               // 4 phases, 4 k (via lanes)
        const int kk    = khi * 16 + p * 4 + kq;  // this thread's k
        const int vbase = kk * 8 + lq;            // + m*256 : a[m,k,l-chunk]
        const int rbase = jb * 256 + kk * 8;      // + jt*256 + mc : a[j,k,m..]

        u64 acc1[4][2], acc2[4][2];               // b64 l-pairs
        #pragma unroll
        for (int jt = 0; jt < 4; ++jt) {
            acc1[jt][0] = 0ull; acc1[jt][1] = 0ull;
            acc2[jt][0] = 0ull; acc2[jt][1] = 0ull;
        }

        #pragma unroll
        for (int mc = 0; mc < 8; ++mc) {        // m = mc*4 + mm
            float4 aj4[4], rj4[4];
            #pragma unroll
            for (int jt = 0; jt < 4; ++jt) {
                aj4[jt] = sc4[ajbase + jt * 8 + mc];    // a[i,jb+jt,m..] bcast
                rj4[jt] = sc4[rbase + jt * 256 + mc];   // a[jb+jt,k,m..]
            }

            #pragma unroll
            for (int mm = 0; mm < 4; ++mm) {
                const int m = mc * 4 + mm;
                ulonglong2 sm2 = *reinterpret_cast<const ulonglong2*>(
                                     &sc4[sibase + m * 8]);     // a[i,m,l..]
                ulonglong2 v2  = *reinterpret_cast<const ulonglong2*>(
                                     &sc4[vbase + m * 256]);    // a[m,k,l..]

                #pragma unroll
                for (int jt = 0; jt < 4; ++jt) {
                    u64 avd = dup2(((const float*)&aj4[jt])[mm]);
                    u64 rvd = dup2(((const float*)&rj4[jt])[mm]);
                    FMA2(acc2[jt][0], avd, v2.x);
                    FMA2(acc2[jt][1], avd, v2.y);
                    FMA2(acc1[jt][0], rvd, sm2.x);
                    FMA2(acc1[jt][1], rvd, sm2.y);
                }
            }
        }

        // ---- KL for this 4j x 4l tile: two * log(two/one) ----
        #pragma unroll
        for (int jt = 0; jt < 4; ++jt)
            #pragma unroll
            for (int h = 0; h < 2; ++h) {
                float t2a, t2b, t1a, t1b;
                unpack2(acc2[jt][h], t2a, t2b);
                unpack2(acc1[jt][h], t1a, t1b);
                kl = fmaf(t2a, acc_logf(__fdividef(t2a, t1a)), kl);
                kl = fmaf(t2b, acc_logf(__fdividef(t2b, t1b)), kl);
            }
    }

    // ---- deterministic block reduction ----
    #pragma unroll
    for (int o = 16; o > 0; o >>= 1)
        kl += __shfl_xor_sync(0xffffffffu, kl, o);

    __shared__ float sred[16];
    __shared__ bool  s_last;
    if ((tid & 31) == 0) sred[w] = kl;
    __syncthreads();

    if (tid == 0) {
        float s = 0.0f;
        #pragma unroll
        for (int x = 0; x < 16; ++x) s += sred[x];
        g_partial[b * 32 + i] = s;
        __threadfence();
        s_last = (atomicAdd(&g_count, 1) == 1023);
    }
    __syncthreads();

    // ---- last CTA: deterministic double-precision final reduce ----
    if (s_last && tid < 32) {
        __threadfence();
        double s = 0.0;
        #pragma unroll
        for (int it = 0; it < 32; ++it)
            s += (double)g_partial[it * 32 + tid];
        #pragma unroll
        for (int o = 16; o > 0; o >>= 1)
            s += __shfl_xor_sync(0xffffffffu, s, o);
        if (tid == 0) {
            out[0] = (float)(s * (1.0 / 32.0));   // / B
            g_count = 0;                          // reset for next graph replay
        }
    }
}

extern "C" void kernel_launch(void* const* d_in, const int* in_sizes, int n_in,
                              void* d_out, int out_size) {
    const float* A = (const float*)d_in[0];
    float* out = (float*)d_out;

    cudaFuncSetAttribute(assoc_kernel,
                         cudaFuncAttributeMaxDynamicSharedMemorySize, 131072);

    dim3 grid(32, 32);   // (i, b)
    assoc_kernel<<<grid, 512, 131072>>>(A, out);
}